// round 14
// baseline (speedup 1.0000x reference)
#include <cuda_runtime.h>
#include <cstdint>

// Problem constants
#define S_LEN   2048
#define HID     2048
#define EMBD    512
#define VOCAB_L 32000LL
#define EOS_ID  2LL
#define NEMB    4

// GEMM tiling: 128x256 CTA tile, BK=64, 2-stage
#define BM 128
#define BN 256
#define BK 64
#define NCHUNK 32                    // NEMB*EMBD/BK
#define NSTAGE 2
#define NTHREADS 512
#define ROWB 256                     // BK * 4 bytes per row
#define A_BYTES (BM * ROWB)          // 32768
#define B_BYTES (BN * ROWB)          // 65536
#define OFF_B   (NSTAGE * A_BYTES)                  // 65536
#define OFF_NID (OFF_B + NSTAGE * B_BYTES)          // 196608
#define SMEM_BYTES (OFF_NID + NEMB * BM * 4)        // 198656

__device__ int g_ids_is64;

__device__ __forceinline__ uint32_t s2u(const void* p) {
    uint32_t a;
    asm("{ .reg .u64 t; cvta.to.shared.u64 t, %1; cvt.u32.u64 %0, t; }"
        : "=r"(a) : "l"(p));
    return a;
}
__device__ __forceinline__ void cp16(uint32_t dst, const void* src) {
    asm volatile("cp.async.cg.shared.global [%0], [%1], 16;"
                 :: "r"(dst), "l"(src) : "memory");
}
__device__ __forceinline__ void ldsm4(uint32_t& r0, uint32_t& r1,
                                      uint32_t& r2, uint32_t& r3, uint32_t a) {
    asm volatile("ldmatrix.sync.aligned.m8n8.x4.shared.b16 {%0,%1,%2,%3}, [%4];"
                 : "=r"(r0), "=r"(r1), "=r"(r2), "=r"(r3) : "r"(a));
}
__device__ __forceinline__ void mma_tf32(float* d, const uint32_t* a,
                                         const uint32_t* b) {
    asm volatile(
        "mma.sync.aligned.m16n8k8.row.col.f32.tf32.tf32.f32 "
        "{%0,%1,%2,%3}, {%4,%5,%6,%7}, {%8,%9}, {%0,%1,%2,%3};"
        : "+f"(d[0]), "+f"(d[1]), "+f"(d[2]), "+f"(d[3])
        : "r"(a[0]), "r"(a[1]), "r"(a[2]), "r"(a[3]), "r"(b[0]), "r"(b[1]));
}

// Detect int64 vs int32 ids transport (odd words all zero => int64 LE, ids<32000)
__global__ void detect_ids_dtype_kernel(const int* __restrict__ ids32) {
    if (threadIdx.x == 0) {
        int nz = 0;
#pragma unroll
        for (int i = 1; i < 128; i += 2) nz |= ids32[i];
        g_ids_is64 = (nz == 0) ? 1 : 0;
    }
}

__device__ __forceinline__ long long load_id(const void* __restrict__ ids,
                                             int i, int is64) {
    if (is64) return ((const long long*)ids)[i];
    return (long long)((const int*)ids)[i];
}

__global__ __launch_bounds__(NTHREADS, 1)
void ngram_emb_mma_kernel(const void* __restrict__ ids,
                          const float* __restrict__ word,
                          const float* __restrict__ e0, const float* __restrict__ e1,
                          const float* __restrict__ e2, const float* __restrict__ e3,
                          const float* __restrict__ p0, const float* __restrict__ p1,
                          const float* __restrict__ p2, const float* __restrict__ p3,
                          float* __restrict__ out)
{
    extern __shared__ char smc[];
    const uint32_t smem_u = s2u(smc);

    const int tid  = threadIdx.x;
    const int wid  = tid >> 5;
    const int lane = tid & 31;
    const int m0   = blockIdx.y * BM;
    const int n0   = blockIdx.x * BN;
    const int is64 = g_ids_is64;

    const float* const embs[NEMB]  = {e0, e1, e2, e3};
    const float* const projs[NEMB] = {p0, p1, p2, p3};

    // ---- hashed ngram indices (EOS segment logic -> <=2 lookbacks) ----
    int* nid = (int*)(smc + OFF_NID);
    if (tid < BM) {
        const int p = m0 + tid;
        const int t = p & (S_LEN - 1);
        const long long id    = load_id(ids, p, is64);
        const long long prev1 = (t >= 1) ? load_id(ids, p - 1, is64) : EOS_ID;
        const long long prev2 = (t >= 2) ? load_id(ids, p - 2, is64) : EOS_ID;
        const bool ok1 = (t >= 1) && (prev1 != EOS_ID);
        const bool ok2 = (t >= 2) && (prev1 != EOS_ID) && (prev2 != EOS_ID);
        const long long s1 = ok1 ? prev1 : 0;
        const long long s2 = ok2 ? prev2 : 0;
#pragma unroll
        for (int e = 0; e < NEMB; e++) {
            const long long dim = 128000LL + 2 * e + 1;
            const long long m1  = VOCAB_L % dim;
            long long ng = id + s1 * m1;
            if (e >= 2) {
                const long long m2 = (m1 * VOCAB_L) % dim;
                ng += s2 * m2;
            }
            nid[e * BM + tid] = (int)(ng % dim);
        }
    }
    __syncthreads();

    // ---- producer mapping: row = tid/4 (0..127), 4 of 16 16B groups ----
    const int prow = tid >> 2;
    const int pgb  = (tid & 3) * 4;       // group base: 0,4,8,12

    // ---- compute mapping: 16 warps as 4(M) x 4(N), warp tile 32x64 ----
    const int wm = (wid >> 2) * 32;
    const int wn = (wid & 3) * 64;
    const int fr = lane >> 2;             // 0..7
    const int fc = lane & 3;              // 0..3
    const int lr = lane & 7;              // ldmatrix row-within-tile

    // ldmatrix per-lane invariants (row & 7 == lr for both operands)
    const uint32_t arow_off = (uint32_t)(wm + lr + ((lane >> 3) & 1) * 8) * ROWB;
    const int      ag_half  = (lane >> 4) & 1;
    const uint32_t brow_off = (uint32_t)(wn + lr + ((lane >> 4) & 1) * 8) * ROWB;
    const int      bg_half  = (lane >> 3) & 1;

    float acc[2][8][4];
#pragma unroll
    for (int i = 0; i < 2; i++)
#pragma unroll
        for (int j = 0; j < 8; j++)
#pragma unroll
            for (int q = 0; q < 4; q++) acc[i][j][q] = 0.0f;

    // SMEM layout: [row][k] row-major, 256B/row, 16B-group swizzle g ^= (row&7).
#define LDGSTS_CHUNK(c, stage)                                                \
    {                                                                         \
        const int e_ = (c) >> 3, k0_ = ((c) & 7) * BK;                        \
        const float* ar_ = embs[e_] +                                         \
            (size_t)nid[e_ * BM + prow] * EMBD + k0_;                         \
        const uint32_t abase_ = smem_u + (stage) * A_BYTES + prow * ROWB;     \
        _Pragma("unroll")                                                     \
        for (int i = 0; i < 4; i++) {                                         \
            const int g_ = pgb + i;                                           \
            cp16(abase_ + ((g_ ^ (prow & 7)) << 4), ar_ + g_ * 4);            \
        }                                                                     \
        _Pragma("unroll")                                                     \
        for (int rb = 0; rb < 2; rb++) {                                      \
            const int row_ = rb * 128 + prow;                                 \
            const float* br_ = projs[e_] +                                    \
                (size_t)(n0 + row_) * EMBD + k0_;                             \
            const uint32_t bbase_ = smem_u + OFF_B + (stage) * B_BYTES +      \
                                    row_ * ROWB;                              \
            _Pragma("unroll")                                                 \
            for (int i = 0; i < 4; i++) {                                     \
                const int g_ = pgb + i;                                       \
                cp16(bbase_ + ((g_ ^ (row_ & 7)) << 4), br_ + g_ * 4);        \
            }                                                                 \
        }                                                                     \
        asm volatile("cp.async.commit_group;" ::: "memory");                  \
    }

#define COMPUTE_CHUNK(stage)                                                  \
    {                                                                         \
        const uint32_t Ab_ = smem_u + (stage) * A_BYTES + arow_off;           \
        const uint32_t Bb_ = smem_u + OFF_B + (stage) * B_BYTES + brow_off;   \
        _Pragma("unroll")                                                     \
        for (int ks = 0; ks < 8; ks++) {                                      \
            const uint32_t aswz = (uint32_t)(((2 * ks + ag_half) ^ lr) << 4); \
            const uint32_t bswz = (uint32_t)(((2 * ks + bg_half) ^ lr) << 4); \
            uint32_t af[2][4], bf[8][2];                                      \
            _Pragma("unroll")                                                 \
            for (int mt = 0; mt < 2; mt++)                                    \
                ldsm4(af[mt][0], af[mt][1], af[mt][2], af[mt][3],             \
                      Ab_ + mt * 16 * ROWB + aswz);                           \
            _Pragma("unroll")                                                 \
            for (int pt = 0; pt < 4; pt++)                                    \
                ldsm4(bf[2 * pt][0], bf[2 * pt][1],                           \
                      bf[2 * pt + 1][0], bf[2 * pt + 1][1],                   \
                      Bb_ + pt * 16 * ROWB + bswz);                           \
            _Pragma("unroll")                                                 \
            for (int mt = 0; mt < 2; mt++)                                    \
                _Pragma("unroll")                                             \
                for (int nt = 0; nt < 8; nt++)                                \
                    mma_tf32(acc[mt][nt], af[mt], bf[nt]);                    \
        }                                                                     \
    }

    // ---- 2-stage mainloop: 32 long chunks ----
    LDGSTS_CHUNK(0, 0);
    LDGSTS_CHUNK(1, 1);

    for (int c = 0; c < NCHUNK; c++) {
        if (c + 2 < NCHUNK) {
            asm volatile("cp.async.wait_group 1;" ::: "memory");
        } else {
            asm volatile("cp.async.wait_group 0;" ::: "memory");
        }
        __syncthreads();
        COMPUTE_CHUNK(c & 1);
        __syncthreads();
        if (c + 2 < NCHUNK) LDGSTS_CHUNK(c + 2, c & 1);
    }

    // ---- epilogue: + word_emb gather, x 1/5 ----
    const float inv = 1.0f / 5.0f;
#pragma unroll
    for (int mt = 0; mt < 2; mt++) {
#pragma unroll
        for (int half = 0; half < 2; half++) {
            const int mr = wm + mt * 16 + fr + half * 8;
            const int mg = m0 + mr;
            const long long tok = load_id(ids, mg, is64);
            const float* __restrict__ wr = word + (size_t)tok * HID;
            float* __restrict__ orow = out + (size_t)mg * HID;
#pragma unroll
            for (int nt = 0; nt < 8; nt++) {
                const int col = n0 + wn + nt * 8 + fc * 2;
                const float2 wv = *(const float2*)(wr + col);
                float2 o;
                o.x = (acc[mt][nt][half * 2 + 0] + wv.x) * inv;
                o.y = (acc[mt][nt][half * 2 + 1] + wv.y) * inv;
                *(float2*)(orow + col) = o;
            }
        }
    }
}

extern "C" void kernel_launch(void* const* d_in, const int* in_sizes, int n_in,
                              void* d_out, int out_size)
{
    // Identify inputs by element count:
    //   ids: 8192 (int32/int64 auto-detected)   word_emb: 65,536,000
    //   emb_e: 65,536,512 + 1024*e              proj_e: 1,048,576 (in order)
    const void* ids = nullptr;
    const float* word = nullptr;
    const float* emb[NEMB]  = {nullptr, nullptr, nullptr, nullptr};
    const float* proj[NEMB] = {nullptr, nullptr, nullptr, nullptr};
    int np = 0;
    int M = 8192;

    for (int i = 0; i < n_in; i++) {
        const long long sz = in_sizes[i];
        if (sz < 1000000) {
            ids = d_in[i];
            M = (int)sz;
        } else if (sz == 65536000LL) {
            word = (const float*)d_in[i];
        } else if (sz == 65536512LL) {
            emb[0] = (const float*)d_in[i];
        } else if (sz == 65537536LL) {
            emb[1] = (const float*)d_in[i];
        } else if (sz == 65538560LL) {
            emb[2] = (const float*)d_in[i];
        } else if (sz == 65539584LL) {
            emb[3] = (const float*)d_in[i];
        } else if (sz == 1048576LL && np < NEMB) {
            proj[np++] = (const float*)d_in[i];
        }
    }

    cudaFuncSetAttribute(ngram_emb_mma_kernel,
                         cudaFuncAttributeMaxDynamicSharedMemorySize, SMEM_BYTES);

    detect_ids_dtype_kernel<<<1, 32>>>((const int*)ids);

    dim3 grid(HID / BN, M / BM);   // (8, 64)
    ngram_emb_mma_kernel<<<grid, NTHREADS, SMEM_BYTES>>>(
        ids, word,
        emb[0], emb[1], emb[2], emb[3],
        proj[0], proj[1], proj[2], proj[3],
        (float*)d_out);
}

// round 17
// speedup vs baseline: 1.2365x; 1.2365x over previous
#include <cuda_runtime.h>
#include <cstdint>

// Problem constants
#define S_LEN   2048
#define HID     2048
#define EMBD    512
#define VOCAB_L 32000LL
#define EOS_ID  2LL
#define NEMB    4

// GEMM tiling (R12 shape)
#define BM 128
#define BN 256
#define BK 32
#define NCHUNK 64                    // NEMB*EMBD/BK
#define NSTAGE 4
#define NTHREADS 512
#define A_BYTES (BM * BK * 4)        // 16384
#define B_BYTES (BN * BK * 4)        // 32768
#define OFF_B   (NSTAGE * A_BYTES)
#define OFF_NID (OFF_B + NSTAGE * B_BYTES)
#define SMEM_BYTES (OFF_NID + NEMB * BM * 4)

__device__ int g_ids_is64;

__device__ __forceinline__ uint32_t s2u(const void* p) {
    uint32_t a;
    asm("{ .reg .u64 t; cvta.to.shared.u64 t, %1; cvt.u32.u64 %0, t; }"
        : "=r"(a) : "l"(p));
    return a;
}
__device__ __forceinline__ void cp16(uint32_t dst, const void* src) {
    asm volatile("cp.async.cg.shared.global [%0], [%1], 16;"
                 :: "r"(dst), "l"(src) : "memory");
}
__device__ __forceinline__ void ldsm4(uint32_t& r0, uint32_t& r1,
                                      uint32_t& r2, uint32_t& r3, uint32_t a) {
    asm volatile("ldmatrix.sync.aligned.m8n8.x4.shared.b16 {%0,%1,%2,%3}, [%4];"
                 : "=r"(r0), "=r"(r1), "=r"(r2), "=r"(r3) : "r"(a));
}
__device__ __forceinline__ void mma_tf32(float* d, const uint32_t* a,
                                         const uint32_t* b) {
    asm volatile(
        "mma.sync.aligned.m16n8k8.row.col.f32.tf32.tf32.f32 "
        "{%0,%1,%2,%3}, {%4,%5,%6,%7}, {%8,%9}, {%0,%1,%2,%3};"
        : "+f"(d[0]), "+f"(d[1]), "+f"(d[2]), "+f"(d[3])
        : "r"(a[0]), "r"(a[1]), "r"(a[2]), "r"(a[3]), "r"(b[0]), "r"(b[1]));
}

// Detect int64 vs int32 ids transport (odd words all zero => int64 LE, ids<32000)
__global__ void detect_ids_dtype_kernel(const int* __restrict__ ids32) {
    if (threadIdx.x == 0) {
        int nz = 0;
#pragma unroll
        for (int i = 1; i < 128; i += 2) nz |= ids32[i];
        g_ids_is64 = (nz == 0) ? 1 : 0;
    }
}

__device__ __forceinline__ long long load_id(const void* __restrict__ ids,
                                             int i, int is64) {
    if (is64) return ((const long long*)ids)[i];
    return (long long)((const int*)ids)[i];
}

__global__ __launch_bounds__(NTHREADS, 1)
void ngram_emb_mma_kernel(const void* __restrict__ ids,
                          const float* __restrict__ word,
                          const float* __restrict__ e0, const float* __restrict__ e1,
                          const float* __restrict__ e2, const float* __restrict__ e3,
                          const float* __restrict__ p0, const float* __restrict__ p1,
                          const float* __restrict__ p2, const float* __restrict__ p3,
                          float* __restrict__ out)
{
    extern __shared__ char smc[];
    const uint32_t smem_u = s2u(smc);

    const int tid  = threadIdx.x;
    const int wid  = tid >> 5;
    const int lane = tid & 31;
    const int m0   = blockIdx.y * BM;
    const int n0   = blockIdx.x * BN;
    const int is64 = g_ids_is64;

    const float* const embs[NEMB]  = {e0, e1, e2, e3};
    const float* const projs[NEMB] = {p0, p1, p2, p3};

    // ---- hashed ngram indices (EOS segment logic -> <=2 lookbacks) ----
    int* nid = (int*)(smc + OFF_NID);
    if (tid < BM) {
        const int p = m0 + tid;
        const int t = p & (S_LEN - 1);
        const long long id    = load_id(ids, p, is64);
        const long long prev1 = (t >= 1) ? load_id(ids, p - 1, is64) : EOS_ID;
        const long long prev2 = (t >= 2) ? load_id(ids, p - 2, is64) : EOS_ID;
        const bool ok1 = (t >= 1) && (prev1 != EOS_ID);
        const bool ok2 = (t >= 2) && (prev1 != EOS_ID) && (prev2 != EOS_ID);
        const long long s1 = ok1 ? prev1 : 0;
        const long long s2 = ok2 ? prev2 : 0;
#pragma unroll
        for (int e = 0; e < NEMB; e++) {
            const long long dim = 128000LL + 2 * e + 1;
            const long long m1  = VOCAB_L % dim;
            long long ng = id + s1 * m1;
            if (e >= 2) {
                const long long m2 = (m1 * VOCAB_L) % dim;
                ng += s2 * m2;
            }
            nid[e * BM + tid] = (int)(ng % dim);
        }
    }
    __syncthreads();

    // ---- producer mapping: row = tid/4, 2 of 8 16B groups per row-block ----
    const int prow = tid >> 2;            // 0..127
    const int pgb  = (tid & 3) * 2;       // group base: 0,2,4,6

    // ---- compute mapping: 16 warps as 4(M) x 4(N), warp tile 32x64 ----
    const int wm = (wid >> 2) * 32;
    const int wn = (wid & 3) * 64;
    const int fr = lane >> 2;             // 0..7
    const int fc = lane & 3;              // 0..3
    const int lr = lane & 7;              // ldmatrix row-within-tile

    // ldmatrix per-lane invariants (row & 7 == lr for both operands)
    const uint32_t arow_off = (uint32_t)(wm + lr + ((lane >> 3) & 1) * 8) * 128;
    const int      ag_half  = (lane >> 4) & 1;
    const uint32_t brow_off = (uint32_t)(wn + lr + ((lane >> 4) & 1) * 8) * 128;
    const int      bg_half  = (lane >> 3) & 1;

    float acc[2][8][4];
#pragma unroll
    for (int i = 0; i < 2; i++)
#pragma unroll
        for (int j = 0; j < 8; j++)
#pragma unroll
            for (int q = 0; q < 4; q++) acc[i][j][q] = 0.0f;

    // SMEM layout: [row][k] row-major, 128B/row, 16B-group swizzle g ^= (row&7).
#define LDGSTS_CHUNK(c, stage)                                                \
    {                                                                         \
        const int e_ = (c) >> 4, k0_ = ((c) & 15) * BK;                       \
        const float* ar_ = embs[e_] +                                         \
            (size_t)nid[e_ * BM + prow] * EMBD + k0_;                         \
        const uint32_t abase_ = smem_u + (stage) * A_BYTES + prow * 128;      \
        _Pragma("unroll")                                                     \
        for (int i = 0; i < 2; i++) {                                         \
            const int g_ = pgb + i;                                           \
            cp16(abase_ + ((g_ ^ (prow & 7)) << 4), ar_ + g_ * 4);            \
        }                                                                     \
        _Pragma("unroll")                                                     \
        for (int rb = 0; rb < 2; rb++) {                                      \
            const int row_ = rb * 128 + prow;                                 \
            const float* br_ = projs[e_] +                                    \
                (size_t)(n0 + row_) * EMBD + k0_;                             \
            const uint32_t bbase_ = smem_u + OFF_B + (stage) * B_BYTES +      \
                                    row_ * 128;                               \
            _Pragma("unroll")                                                 \
            for (int i = 0; i < 2; i++) {                                     \
                const int g_ = pgb + i;                                       \
                cp16(bbase_ + ((g_ ^ (row_ & 7)) << 4), br_ + g_ * 4);        \
            }                                                                 \
        }                                                                     \
    }

// fragment-load helpers (one ks-step's worth)
#define LDSM_A(buf, ks)                                                       \
    {                                                                         \
        const uint32_t aswz =                                                 \
            (uint32_t)(((2 * (ks) + ag_half) ^ lr) << 4);                     \
        _Pragma("unroll")                                                     \
        for (int mt = 0; mt < 2; mt++)                                        \
            ldsm4(af[buf][mt][0], af[buf][mt][1],                             \
                  af[buf][mt][2], af[buf][mt][3],                             \
                  Ab_ + mt * 2048 + aswz);                                    \
    }
#define LDSM_B(buf, ks)                                                       \
    {                                                                         \
        const uint32_t bswz =                                                 \
            (uint32_t)(((2 * (ks) + bg_half) ^ lr) << 4);                     \
        _Pragma("unroll")                                                     \
        for (int pt = 0; pt < 4; pt++)                                        \
            ldsm4(bf[buf][2 * pt][0], bf[buf][2 * pt][1],                     \
                  bf[buf][2 * pt + 1][0], bf[buf][2 * pt + 1][1],             \
                  Bb_ + pt * 2048 + bswz);                                    \
    }

#define COMPUTE_CHUNK(stage)                                                  \
    {                                                                         \
        const uint32_t Ab_ = smem_u + (stage) * A_BYTES + arow_off;           \
        const uint32_t Bb_ = smem_u + OFF_B + (stage) * B_BYTES + brow_off;   \
        uint32_t af[2][2][4], bf[2][8][2];                                    \
        LDSM_A(0, 0);                                                         \
        LDSM_B(0, 0);                                                         \
        _Pragma("unroll")                                                     \
        for (int ks = 0; ks < 4; ks++) {                                      \
            const int cur = ks & 1, nxt = cur ^ 1;                            \
            if (ks < 3) {                                                     \
                LDSM_A(nxt, ks + 1);                                          \
                LDSM_B(nxt, ks + 1);                                          \
            }                                                                 \
            _Pragma("unroll")                                                 \
            for (int mt = 0; mt < 2; mt++)                                    \
                _Pragma("unroll")                                             \
                for (int nt = 0; nt < 8; nt++)                                \
                    mma_tf32(acc[mt][nt], af[cur][mt], bf[cur][nt]);          \
        }                                                                     \
    }

    // ---- 4-stage mainloop, ONE sync per chunk, loads before compute ----
    LDGSTS_CHUNK(0, 0);
    asm volatile("cp.async.commit_group;" ::: "memory");
    LDGSTS_CHUNK(1, 1);
    asm volatile("cp.async.commit_group;" ::: "memory");
    LDGSTS_CHUNK(2, 2);
    asm volatile("cp.async.commit_group;" ::: "memory");

    for (int c = 0; c < NCHUNK; c++) {
        asm volatile("cp.async.wait_group 2;" ::: "memory");
        __syncthreads();
        if (c + 3 < NCHUNK) LDGSTS_CHUNK(c + 3, (c + 3) & (NSTAGE - 1));
        asm volatile("cp.async.commit_group;" ::: "memory");   // empty in tail
        COMPUTE_CHUNK(c & (NSTAGE - 1));
    }

    // ---- epilogue: + word_emb gather, x 1/5 ----
    const float inv = 1.0f / 5.0f;
#pragma unroll
    for (int mt = 0; mt < 2; mt++) {
#pragma unroll
        for (int half = 0; half < 2; half++) {
            const int mr = wm + mt * 16 + fr + half * 8;
            const int mg = m0 + mr;
            const long long tok = load_id(ids, mg, is64);
            const float* __restrict__ wr = word + (size_t)tok * HID;
            float* __restrict__ orow = out + (size_t)mg * HID;
#pragma unroll
            for (int nt = 0; nt < 8; nt++) {
                const int col = n0 + wn + nt * 8 + fc * 2;
                const float2 wv = *(const float2*)(wr + col);
                float2 o;
                o.x = (acc[mt][nt][half * 2 + 0] + wv.x) * inv;
                o.y = (acc[mt][nt][half * 2 + 1] + wv.y) * inv;
                *(float2*)(orow + col) = o;
            }
        }
    }
}

extern "C" void kernel_launch(void* const* d_in, const int* in_sizes, int n_in,
                              void* d_out, int out_size)
{
    // Identify inputs by element count:
    //   ids: 8192 (int32/int64 auto-detected)   word_emb: 65,536,000
    //   emb_e: 65,536,512 + 1024*e              proj_e: 1,048,576 (in order)
    const void* ids = nullptr;
    const float* word = nullptr;
    const float* emb[NEMB]  = {nullptr, nullptr, nullptr, nullptr};
    const float* proj[NEMB] = {nullptr, nullptr, nullptr, nullptr};
    int np = 0;
    int M = 8192;

    for (int i = 0; i < n_in; i++) {
        const long long sz = in_sizes[i];
        if (sz < 1000000) {
            ids = d_in[i];
            M = (int)sz;
        } else if (sz == 65536000LL) {
            word = (const float*)d_in[i];
        } else if (sz == 65536512LL) {
            emb[0] = (const float*)d_in[i];
        } else if (sz == 65537536LL) {
            emb[1] = (const float*)d_in[i];
        } else if (sz == 65538560LL) {
            emb[2] = (const float*)d_in[i];
        } else if (sz == 65539584LL) {
            emb[3] = (const float*)d_in[i];
        } else if (sz == 1048576LL && np < NEMB) {
            proj[np++] = (const float*)d_in[i];
        }
    }

    cudaFuncSetAttribute(ngram_emb_mma_kernel,
                         cudaFuncAttributeMaxDynamicSharedMemorySize, SMEM_BYTES);

    detect_ids_dtype_kernel<<<1, 32>>>((const int*)ids);

    dim3 grid(HID / BN, M / BM);   // (8, 64)
    ngram_emb_mma_kernel<<<grid, NTHREADS, SMEM_BYTES>>>(
        ids, word,
        emb[0], emb[1], emb[2], emb[3],
        proj[0], proj[1], proj[2], proj[3],
        (float*)d_out);
}